// round 3
// baseline (speedup 1.0000x reference)
#include <cuda_runtime.h>
#include <cstdint>

// ---------------- problem constants ----------------
#define BATCH 2
#define NPTS 100000
#define TOTPTS (BATCH * NPTS)
#define NV 32
#define VOX 32768            // 32^3
#define C0 256               // voxel feature channels
#define C1 512               // conv1 out
#define C2 1024              // conv2 out

// ---------------- device scratch (no allocs allowed) ----------------
__device__ float g_grid[BATCH * C0 * VOX];      // (B, 256, 32,32,32)  64 MB
__device__ float g_h[TOTPTS * 128];             // per-point hidden    102 MB
__device__ int   g_flat[TOTPTS];
__device__ float g_l2[BATCH * C2 * 512];        // (B, 1024, 8^3)      4 MB
__device__ float g_WtT[8 * 1024 * 512];         // (par, ci, co)       16 MB

// ---------------- zero the scatter grid (needed every replay) ----------------
__global__ void zero_grid_kernel() {
    float4* p = reinterpret_cast<float4*>(g_grid);
    int n4 = (BATCH * C0 * VOX) / 4;
    for (int i = blockIdx.x * blockDim.x + threadIdx.x; i < n4; i += gridDim.x * blockDim.x)
        p[i] = make_float4(0.f, 0.f, 0.f, 0.f);
}

// ---------------- transpose Wt (1024,512,2,2,2) -> (par,ci,co) ----------------
__global__ void wt_transpose_kernel(const float* __restrict__ Wt) {
    int i = blockIdx.x * blockDim.x + threadIdx.x;   // out index
    if (i >= 8 * 1024 * 512) return;
    int co  = i & 511;
    int ci  = (i >> 9) & 1023;
    int par = i >> 19;
    g_WtT[i] = Wt[ci * 4096 + co * 8 + par];
}

// ---------------- point MLP stage 1: h = relu(W1 @ xc + b1), + flat index ----------------
__global__ __launch_bounds__(256) void point_h_kernel(
    const float* __restrict__ pc, const float* __restrict__ W1, const float* __restrict__ b1)
{
    __shared__ float W1s[384];
    __shared__ float b1s[128];
    int tid = threadIdx.x;
    // FIX (R2): stage with loops — blockDim is 256, arrays are 384+128.
    for (int i = tid; i < 384; i += 256) W1s[i] = W1[i];
    if (tid < 128) b1s[tid] = b1[tid];
    __syncthreads();

    int P = blockIdx.x * 8 + (tid >> 5);      // 8 points / block, 1 warp each
    int lane = tid & 31;
    if (P >= TOTPTS) return;

    float x = pc[P * 3 + 0], y = pc[P * 3 + 1], z = pc[P * 3 + 2];
    int ix = (int)floorf((x + 1.0f) * 16.0f);
    int iy = (int)floorf((y + 1.0f) * 16.0f);
    int iz = (int)floorf((z + 1.0f) * 16.0f);
    float xcx = x - (ix * 0.0625f + 0.03125f - 1.0f);
    float xcy = y - (iy * 0.0625f + 0.03125f - 1.0f);
    float xcz = z - (iz * 0.0625f + 0.03125f - 1.0f);

    if (lane == 0) g_flat[P] = ix * 1024 + iy * 32 + iz;

    float* hrow = g_h + (long)P * 128;
#pragma unroll
    for (int j = 0; j < 4; j++) {
        int o = lane + 32 * j;
        float v = W1s[o * 3 + 0] * xcx + W1s[o * 3 + 1] * xcy + W1s[o * 3 + 2] * xcz + b1s[o];
        hrow[o] = fmaxf(v, 0.0f);
    }
}

// ---------------- point MLP stage 2: f = relu(W2 @ h + b2) -> atomicMax scatter ----------------
// tile: 64 points, all 256 couts. smem: W2 transposed (stride 257), h transposed (stride 65).
__global__ __launch_bounds__(256) void point_f_scatter_kernel(
    const float* __restrict__ W2, const float* __restrict__ b2)
{
    extern __shared__ float sm[];
    float* W2s = sm;                 // [k][o] stride 257  (128*257)
    float* hs  = sm + 128 * 257;     // [k][p] stride 65   (128*65)
    int tid = threadIdx.x;
    int P0 = blockIdx.x * 64;

    for (int idx = tid; idx < 256 * 128; idx += 256) {
        int o = idx >> 7, k = idx & 127;
        W2s[k * 257 + o] = W2[idx];            // W2 is [o][k], idx = o*128+k
    }
    const float* hsrc = g_h + (long)P0 * 128;
    for (int idx = tid; idx < 64 * 128; idx += 256) {
        int p = idx >> 7, k = idx & 127;
        hs[k * 65 + p] = hsrc[idx];
    }
    __syncthreads();

    int cg = tid & 31;     // cout lane: co = cg + 32*j
    int pg = tid >> 5;     // point group: p = pg*8 + i
    float acc[8][8];
#pragma unroll
    for (int i = 0; i < 8; i++)
#pragma unroll
        for (int j = 0; j < 8; j++) acc[i][j] = 0.0f;

#pragma unroll 4
    for (int k = 0; k < 128; k++) {
        float hv[8], wv[8];
#pragma unroll
        for (int i = 0; i < 8; i++) hv[i] = hs[k * 65 + pg * 8 + i];   // warp broadcast
#pragma unroll
        for (int j = 0; j < 8; j++) wv[j] = W2s[k * 257 + cg + 32 * j]; // conflict-free
#pragma unroll
        for (int i = 0; i < 8; i++)
#pragma unroll
            for (int j = 0; j < 8; j++) acc[i][j] = fmaf(hv[i], wv[j], acc[i][j]);
    }

    float bv[8];
#pragma unroll
    for (int j = 0; j < 8; j++) bv[j] = __ldg(&b2[cg + 32 * j]);

    int* ggrid = reinterpret_cast<int*>(g_grid);
#pragma unroll
    for (int i = 0; i < 8; i++) {
        int P = P0 + pg * 8 + i;
        int b = P / NPTS;
        int flat = g_flat[P];
        int base = (b * C0) * VOX + flat;
#pragma unroll
        for (int j = 0; j < 8; j++) {
            float f = acc[i][j] + bv[j];
            if (f > 0.0f)
                atomicMax(&ggrid[base + (cg + 32 * j) * VOX], __float_as_int(f));
        }
    }
}

// ---------------- generic fused conv3x3x3 + bias + relu + maxpool2 ----------------
// CTA: 4x4x4 pooled tile (8^3 pre-pool, 10^3 halo) x 32 couts. cin chunks of 8.
// thread: 1 pooled pos (tid&63) x 8 couts ((tid>>6)*8..) -> 8 pre-pool x 8 cout accs.
__global__ __launch_bounds__(256) void conv_relu_pool_kernel(
    const float* __restrict__ in, const float* __restrict__ w, const float* __restrict__ bias,
    float* __restrict__ out,
    int Cin, int S, long in_bstride, int Sout, long out_bstride)
{
    extern __shared__ float sm[];
    float* in_sh = sm;          // [8][10][10][10] = 8000
    float* w_sh  = sm + 8000;   // [32][8][27]     = 6912

    int St = Sout >> 2;
    int tile = blockIdx.x;
    int txi = tile % St, tyi = (tile / St) % St, tzi = tile / (St * St);
    int co0 = blockIdx.y * 32;
    int b = blockIdx.z;
    int tid = threadIdx.x;
    int p = tid & 63;
    int plx = p & 3, ply = (p >> 2) & 3, plz = p >> 4;
    int cosub = tid >> 6;                   // 0..3

    int bz = tzi * 8 - 1, by = tyi * 8 - 1, bx = txi * 8 - 1;
    const float* inb = in + (long)b * in_bstride;
    int S2 = S * S, S3 = S2 * S;

    float acc[8][8];
#pragma unroll
    for (int a = 0; a < 8; a++)
#pragma unroll
        for (int j = 0; j < 8; j++) acc[a][j] = 0.0f;

    for (int ci0 = 0; ci0 < Cin; ci0 += 8) {
        __syncthreads();
        for (int idx = tid; idx < 8000; idx += 256) {
            int ci = idx / 1000; int r = idx - ci * 1000;
            int z = r / 100; int r2 = r - z * 100;
            int y = r2 / 10; int x = r2 - y * 10;
            int gz = bz + z, gy = by + y, gx = bx + x;
            float v = 0.0f;
            if ((unsigned)gz < (unsigned)S && (unsigned)gy < (unsigned)S && (unsigned)gx < (unsigned)S)
                v = inb[(long)(ci0 + ci) * S3 + gz * S2 + gy * S + gx];
            in_sh[idx] = v;
        }
        for (int idx = tid; idx < 6912; idx += 256) {
            int co = idx / 216; int r = idx - co * 216;
            int ci = r / 27; int k = r - ci * 27;
            w_sh[idx] = w[(long)(co0 + co) * Cin * 27 + (long)(ci0 + ci) * 27 + k];
        }
        __syncthreads();

        for (int ci = 0; ci < 8; ci++) {
            int ibase = ci * 1000;
            int wbase = cosub * 8 * 216 + ci * 27;
            for (int kz = 0; kz < 3; kz++) {
                for (int ky = 0; ky < 3; ky++) {
#pragma unroll
                    for (int kx = 0; kx < 3; kx++) {
                        int k = (kz * 3 + ky) * 3 + kx;
                        float wv[8];
#pragma unroll
                        for (int j = 0; j < 8; j++) wv[j] = w_sh[wbase + j * 216 + k]; // broadcast
                        int zb = ibase + (plz * 2 + kz) * 100 + (ply * 2 + ky) * 10 + (plx * 2 + kx);
#pragma unroll
                        for (int dz = 0; dz < 2; dz++)
#pragma unroll
                            for (int dy = 0; dy < 2; dy++)
#pragma unroll
                                for (int dx = 0; dx < 2; dx++) {
                                    float iv = in_sh[zb + dz * 100 + dy * 10 + dx];
                                    int a = dz * 4 + dy * 2 + dx;
#pragma unroll
                                    for (int j = 0; j < 8; j++)
                                        acc[a][j] = fmaf(iv, wv[j], acc[a][j]);
                                }
                    }
                }
            }
        }
    }

    int So2 = Sout * Sout;
    long So3 = (long)Sout * So2;
    int s = (tzi * 4 + plz) * So2 + (tyi * 4 + ply) * Sout + (txi * 4 + plx);
#pragma unroll
    for (int j = 0; j < 8; j++) {
        int co = co0 + cosub * 8 + j;
        float m = acc[0][j];
#pragma unroll
        for (int a = 1; a < 8; a++) m = fmaxf(m, acc[a][j]);
        out[(long)b * out_bstride + (long)co * So3 + s] = fmaxf(m + __ldg(&bias[co]), 0.0f);
    }
}

// ---------------- convT: 8 parity GEMMs (512co x 512pos) @ K=1024 ----------------
__global__ __launch_bounds__(256) void convt_kernel(const float* __restrict__ bt, float* __restrict__ out) {
    __shared__ float w_sh[32 * 128];
    __shared__ float x_sh[32 * 64];
    int posT = blockIdx.x;          // 8 tiles of 64 positions
    int coT  = blockIdx.y;          // 4 tiles of 128 couts
    int bp   = blockIdx.z;          // b*8 + par
    int b = bp >> 3, par = bp & 7;
    int tid = threadIdx.x;
    int col = tid & 31, prow = tid >> 5;

    const float* wbase = g_WtT + (long)par * (1024 * 512);
    const float* xbase = g_l2 + (long)b * (C2 * 512);

    float acc[4][8];
#pragma unroll
    for (int jc = 0; jc < 4; jc++)
#pragma unroll
        for (int jp = 0; jp < 8; jp++) acc[jc][jp] = 0.0f;

    for (int ci0 = 0; ci0 < 1024; ci0 += 32) {
        __syncthreads();
        for (int idx = tid; idx < 32 * 128; idx += 256) {
            int k = idx >> 7, c = idx & 127;
            w_sh[idx] = wbase[(long)(ci0 + k) * 512 + coT * 128 + c];
        }
        for (int idx = tid; idx < 32 * 64; idx += 256) {
            int k = idx >> 6, pp = idx & 63;
            x_sh[idx] = xbase[(long)(ci0 + k) * 512 + posT * 64 + pp];
        }
        __syncthreads();
#pragma unroll 4
        for (int k = 0; k < 32; k++) {
            float xv[8], wv[4];
#pragma unroll
            for (int jp = 0; jp < 8; jp++) xv[jp] = x_sh[k * 64 + prow + 8 * jp];
#pragma unroll
            for (int jc = 0; jc < 4; jc++) wv[jc] = w_sh[k * 128 + col + 32 * jc];
#pragma unroll
            for (int jc = 0; jc < 4; jc++)
#pragma unroll
                for (int jp = 0; jp < 8; jp++) acc[jc][jp] = fmaf(wv[jc], xv[jp], acc[jc][jp]);
        }
    }

    int az = par >> 2, ay = (par >> 1) & 1, ax = par & 1;
#pragma unroll
    for (int jc = 0; jc < 4; jc++) {
        int co = coT * 128 + col + 32 * jc;
        float bv = __ldg(&bt[co]);
#pragma unroll
        for (int jp = 0; jp < 8; jp++) {
            int pos = posT * 64 + prow + 8 * jp;
            int iz = pos >> 6, iy = (pos >> 3) & 7, ix = pos & 7;
            int s = (2 * iz + az) * 256 + (2 * iy + ay) * 16 + (2 * ix + ax);
            out[((long)b * 1024 + 512 + co) * 4096 + s] = acc[jc][jp] + bv;
        }
    }
}

// ---------------- launcher ----------------
extern "C" void kernel_launch(void* const* d_in, const int* in_sizes, int n_in,
                              void* d_out, int out_size)
{
    const float* pc  = (const float*)d_in[0];
    const float* W1  = (const float*)d_in[1];
    const float* b1  = (const float*)d_in[2];
    const float* W2  = (const float*)d_in[3];
    const float* b2  = (const float*)d_in[4];
    const float* Wc1 = (const float*)d_in[5];
    const float* bc1 = (const float*)d_in[6];
    const float* Wc2 = (const float*)d_in[7];
    const float* bc2 = (const float*)d_in[8];
    const float* Wt  = (const float*)d_in[9];
    const float* bt  = (const float*)d_in[10];
    float* out = (float*)d_out;

    void* p_grid_v; cudaGetSymbolAddress(&p_grid_v, g_grid);
    void* p_l2_v;   cudaGetSymbolAddress(&p_l2_v, g_l2);
    const float* p_grid = (const float*)p_grid_v;
    float* p_l2 = (float*)p_l2_v;

    const int smem_pf = (128 * 257 + 128 * 65) * 4;       // 164,864 B
    const int smem_cv = (8000 + 6912) * 4;                // 59,648 B
    cudaFuncSetAttribute(point_f_scatter_kernel, cudaFuncAttributeMaxDynamicSharedMemorySize, smem_pf);
    cudaFuncSetAttribute(conv_relu_pool_kernel,  cudaFuncAttributeMaxDynamicSharedMemorySize, smem_cv);

    // 1. zero scatter grid (replay-safe)
    zero_grid_kernel<<<2048, 256>>>();
    // 2. transpose Wt for coalesced convT
    wt_transpose_kernel<<<(8 * 1024 * 512 + 255) / 256, 256>>>(Wt);
    // 3. per-point hidden layer
    point_h_kernel<<<TOTPTS / 8, 256>>>(pc, W1, b1);
    // 4. per-point features + voxel max-scatter
    point_f_scatter_kernel<<<TOTPTS / 64, 256, smem_pf>>>(W2, b2);
    // 5. conv1 (256->512, 32^3) + relu + pool -> d_out channels [0,512)
    conv_relu_pool_kernel<<<dim3(64, 16, 2), 256, smem_cv>>>(
        p_grid, Wc1, bc1, out, 256, 32, (long)256 * 32768, 16, (long)1024 * 4096);
    // 6. conv2 (512->1024, 16^3) + relu + pool -> g_l2   (reads l1 from d_out)
    conv_relu_pool_kernel<<<dim3(8, 32, 2), 256, smem_cv>>>(
        out, Wc2, bc2, p_l2, 512, 16, (long)1024 * 4096, 8, (long)1024 * 512);
    // 7. transpose conv -> d_out channels [512,1024)
    convt_kernel<<<dim3(8, 4, 16), 256>>>(bt, out);
}

// round 6
// speedup vs baseline: 2.1003x; 2.1003x over previous
#include <cuda_runtime.h>
#include <cstdint>

// ---------------- problem constants ----------------
#define BATCH 2
#define NPTS 100000
#define TOTPTS (BATCH * NPTS)
#define C0 256
#define C1 512
#define C2 1024
#define SP1 34                 // padded 32+2
#define NPAD1 (SP1*SP1*SP1)    // 39304
#define SP2 18                 // padded 16+2
#define NPAD2 (SP2*SP2*SP2)    // 5832
#define STG 20                 // staging smem row stride (conflict-free frag loads)
#define DST 132                // epilogue smem row stride

// ---------------- device scratch ----------------
__device__ float g_xpad[BATCH * NPAD1 * C0];     // conv1 input, pos-major   80.5 MB
__device__ float g_h[TOTPTS * 128];              // point hidden             102 MB
__device__ int   g_flat[TOTPTS];                 // padded voxel index
__device__ float g_wk1[27 * C1 * C0];            // conv1 W [k][co][ci]      14 MB
__device__ float g_wk2[27 * C2 * C1];            // conv2 W [k][co][ci]      56.6 MB
__device__ float g_c1[BATCH * NPAD1 * C1];       // conv1 pre-pool pos-major 161 MB
__device__ float g_l1pad[BATCH * NPAD2 * C1];    // pooled l1, pos-major     23.9 MB
__device__ float g_c2[BATCH * NPAD2 * C2];       // conv2 pre-pool pos-major 47.8 MB
__device__ float g_l2[BATCH * C2 * 512];         // pooled l2, chan-major    4 MB
__device__ float g_WtT[8 * 1024 * 512];          // convT W (par,ci,co)      16 MB

// ---------------- helpers ----------------
__device__ __forceinline__ uint32_t f2tf(float x) {
    uint32_t u;
    asm("cvt.rna.tf32.f32 %0, %1;" : "=r"(u) : "f"(x));
    return u;
}
__device__ __forceinline__ void mma_tf32(float* c, const uint32_t* a, const uint32_t* b) {
    asm volatile(
        "mma.sync.aligned.m16n8k8.row.col.f32.tf32.tf32.f32 "
        "{%0,%1,%2,%3}, {%4,%5,%6,%7}, {%8,%9}, {%0,%1,%2,%3};\n"
        : "+f"(c[0]), "+f"(c[1]), "+f"(c[2]), "+f"(c[3])
        : "r"(a[0]), "r"(a[1]), "r"(a[2]), "r"(a[3]), "r"(b[0]), "r"(b[1]));
}

// ---------------- zero scratch (replay-safe) ----------------
__global__ void zero_scratch_kernel() {
    float4* p1 = reinterpret_cast<float4*>(g_xpad);
    int n1 = (BATCH * NPAD1 * C0) / 4;
    for (int i = blockIdx.x * blockDim.x + threadIdx.x; i < n1; i += gridDim.x * blockDim.x)
        p1[i] = make_float4(0.f, 0.f, 0.f, 0.f);
    float4* p2 = reinterpret_cast<float4*>(g_l1pad);
    int n2 = (BATCH * NPAD2 * C1) / 4;
    for (int i = blockIdx.x * blockDim.x + threadIdx.x; i < n2; i += gridDim.x * blockDim.x)
        p2[i] = make_float4(0.f, 0.f, 0.f, 0.f);
}

// ---------------- conv weight transpose [co][ci][27] -> [k][co][ci] ----------------
__global__ void wk_transpose_kernel(const float* __restrict__ w, float* __restrict__ wk, int Cout, int Cin) {
    long total = (long)27 * Cout * Cin;
    for (long i = (long)blockIdx.x * blockDim.x + threadIdx.x; i < total; i += (long)gridDim.x * blockDim.x) {
        int ci = (int)(i % Cin);
        long r = i / Cin;
        int co = (int)(r % Cout);
        int k  = (int)(r / Cout);
        wk[i] = w[((long)co * Cin + ci) * 27 + k];
    }
}

// ---------------- convT weight transpose (1024,512,2,2,2) -> (par,ci,co) ----------------
__global__ void wt_transpose_kernel(const float* __restrict__ Wt) {
    int i = blockIdx.x * blockDim.x + threadIdx.x;
    if (i >= 8 * 1024 * 512) return;
    int co = i & 511;
    int ci = (i >> 9) & 1023;
    int par = i >> 19;
    g_WtT[i] = Wt[ci * 4096 + co * 8 + par];
}

// ---------------- point MLP stage 1 ----------------
__global__ __launch_bounds__(256) void point_h_kernel(
    const float* __restrict__ pc, const float* __restrict__ W1, const float* __restrict__ b1)
{
    __shared__ float W1s[384];
    __shared__ float b1s[128];
    int tid = threadIdx.x;
    for (int i = tid; i < 384; i += 256) W1s[i] = W1[i];
    if (tid < 128) b1s[tid] = b1[tid];
    __syncthreads();

    int P = blockIdx.x * 8 + (tid >> 5);
    int lane = tid & 31;
    if (P >= TOTPTS) return;

    float x = pc[P * 3 + 0], y = pc[P * 3 + 1], z = pc[P * 3 + 2];
    int ix = (int)floorf((x + 1.0f) * 16.0f);
    int iy = (int)floorf((y + 1.0f) * 16.0f);
    int iz = (int)floorf((z + 1.0f) * 16.0f);
    float xcx = x - (ix * 0.0625f + 0.03125f - 1.0f);
    float xcy = y - (iy * 0.0625f + 0.03125f - 1.0f);
    float xcz = z - (iz * 0.0625f + 0.03125f - 1.0f);

    if (lane == 0) g_flat[P] = (ix + 1) * (SP1 * SP1) + (iy + 1) * SP1 + (iz + 1);  // padded pos

    float* hrow = g_h + (long)P * 128;
#pragma unroll
    for (int j = 0; j < 4; j++) {
        int o = lane + 32 * j;
        float v = W1s[o * 3 + 0] * xcx + W1s[o * 3 + 1] * xcy + W1s[o * 3 + 2] * xcz + b1s[o];
        hrow[o] = fmaxf(v, 0.0f);
    }
}

// ---------------- point MLP stage 2 + scatter-max into pos-major padded grid ----------------
__global__ __launch_bounds__(256) void point_f_scatter_kernel(
    const float* __restrict__ W2, const float* __restrict__ b2)
{
    extern __shared__ float sm[];
    float* W2s = sm;                 // [k][o] stride 257
    float* hs  = sm + 128 * 257;     // [k][p] stride 65
    int tid = threadIdx.x;
    int P0 = blockIdx.x * 64;

    for (int idx = tid; idx < 256 * 128; idx += 256) {
        int o = idx >> 7, k = idx & 127;
        W2s[k * 257 + o] = W2[idx];
    }
    const float* hsrc = g_h + (long)P0 * 128;
    for (int idx = tid; idx < 64 * 128; idx += 256) {
        int p = idx >> 7, k = idx & 127;
        hs[k * 65 + p] = hsrc[idx];
    }
    __syncthreads();

    int cg = tid & 31;
    int pg = tid >> 5;
    float acc[8][8];
#pragma unroll
    for (int i = 0; i < 8; i++)
#pragma unroll
        for (int j = 0; j < 8; j++) acc[i][j] = 0.0f;

#pragma unroll 4
    for (int k = 0; k < 128; k++) {
        float hv[8], wv[8];
#pragma unroll
        for (int i = 0; i < 8; i++) hv[i] = hs[k * 65 + pg * 8 + i];
#pragma unroll
        for (int j = 0; j < 8; j++) wv[j] = W2s[k * 257 + cg + 32 * j];
#pragma unroll
        for (int i = 0; i < 8; i++)
#pragma unroll
            for (int j = 0; j < 8; j++) acc[i][j] = fmaf(hv[i], wv[j], acc[i][j]);
    }

    float bv[8];
#pragma unroll
    for (int j = 0; j < 8; j++) bv[j] = __ldg(&b2[cg + 32 * j]);

    int* gx = reinterpret_cast<int*>(g_xpad);
#pragma unroll
    for (int i = 0; i < 8; i++) {
        int P = P0 + pg * 8 + i;
        int b = P / NPTS;
        long base = ((long)b * NPAD1 + g_flat[P]) * C0;
#pragma unroll
        for (int j = 0; j < 8; j++) {
            float f = acc[i][j] + bv[j];
            if (f > 0.0f)
                atomicMax(&gx[base + cg + 32 * j], __float_as_int(f));
        }
    }
}

// ---------------- tf32 mma.sync implicit-GEMM conv3x3x3 (+bias+relu) ----------------
// CTA: M=128 co x N=128 padded positions; K = 27 taps x Cin in 16-ci chunks.
// 8 warps in 2(M) x 4(N); warp tile 64x32 via m16n8k8; reg-prefetch pipeline.
__global__ __launch_bounds__(256, 2) void gemm_conv_mma(
    const float* __restrict__ wk,     // [27][Cout][Cin]
    const float* __restrict__ xp,     // [b][Npos][Cin]  (zero padded borders)
    const float* __restrict__ bias,
    float* __restrict__ outp,         // [b][Npos][Cout] pre-pool, pos-major
    int Cin, int ncShift, int Sp, int Npos, int Cout)
{
    extern __shared__ float sh[];
    uint32_t* Ash = reinterpret_cast<uint32_t*>(sh);   // [128][STG]
    uint32_t* Bsh = Ash + 128 * STG;                   // [128][STG]

    int tid = threadIdx.x;
    int lane = tid & 31, wid = tid >> 5;
    int g = lane >> 2, t = lane & 3;
    int wm = wid >> 2, wn = wid & 3;
    int NB = blockIdx.x << 7;
    int M0 = blockIdx.y << 7;
    long bq = (long)blockIdx.z * Npos;
    int total = 27 << ncShift;
    int ncMask = (1 << ncShift) - 1;

    int rowL = tid >> 2;              // 0..63 (load row, +64 for q=1)
    int c4 = (tid & 3) << 2;          // load col group

    float acc[4][4][4];
#pragma unroll
    for (int fm = 0; fm < 4; fm++)
#pragma unroll
        for (int fn = 0; fn < 4; fn++)
#pragma unroll
            for (int r = 0; r < 4; r++) acc[fm][fn][r] = 0.0f;

    uint32_t pa[8], pb[8];

    auto load_chunk = [&](int c) {
        int tap = c >> ncShift;
        int ci0 = (c & ncMask) << 4;
        int k0 = tap / 9; int rr = tap - 9 * k0; int k1 = rr / 3; int k2 = rr - 3 * k1;
        int drow = (k0 - 1) * Sp * Sp + (k1 - 1) * Sp + (k2 - 1);
#pragma unroll
        for (int q = 0; q < 2; q++) {
            int row = rowL + (q << 6);
            float4 av = *reinterpret_cast<const float4*>(
                wk + ((long)tap * Cout + M0 + row) * Cin + ci0 + c4);
            pa[q * 4 + 0] = f2tf(av.x); pa[q * 4 + 1] = f2tf(av.y);
            pa[q * 4 + 2] = f2tf(av.z); pa[q * 4 + 3] = f2tf(av.w);
            int gpos = NB + drow + row;
            float4 bv = make_float4(0.f, 0.f, 0.f, 0.f);
            if ((unsigned)gpos < (unsigned)Npos)
                bv = *reinterpret_cast<const float4*>(xp + (bq + gpos) * Cin + ci0 + c4);
            pb[q * 4 + 0] = f2tf(bv.x); pb[q * 4 + 1] = f2tf(bv.y);
            pb[q * 4 + 2] = f2tf(bv.z); pb[q * 4 + 3] = f2tf(bv.w);
        }
    };

    load_chunk(0);
    for (int c = 0; c < total; c++) {
        __syncthreads();
#pragma unroll
        for (int q = 0; q < 2; q++) {
            int row = rowL + (q << 6);
#pragma unroll
            for (int j = 0; j < 4; j++) {
                Ash[row * STG + c4 + j] = pa[q * 4 + j];
                Bsh[row * STG + c4 + j] = pb[q * 4 + j];
            }
        }
        __syncthreads();
        if (c + 1 < total) load_chunk(c + 1);

#pragma unroll
        for (int ks = 0; ks < 2; ks++) {
            uint32_t af[4][4], bf[4][2];
            int kc = (ks << 3) + t;
#pragma unroll
            for (int fm = 0; fm < 4; fm++) {
                int r0 = (wm << 6) + (fm << 4) + g;
                af[fm][0] = Ash[r0 * STG + kc];
                af[fm][1] = Ash[(r0 + 8) * STG + kc];
                af[fm][2] = Ash[r0 * STG + kc + 4];
                af[fm][3] = Ash[(r0 + 8) * STG + kc + 4];
            }
#pragma unroll
            for (int fn = 0; fn < 4; fn++) {
                int n0 = (wn << 5) + (fn << 3) + g;
                bf[fn][0] = Bsh[n0 * STG + kc];
                bf[fn][1] = Bsh[n0 * STG + kc + 4];
            }
#pragma unroll
            for (int fm = 0; fm < 4; fm++)
#pragma unroll
                for (int fn = 0; fn < 4; fn++)
                    mma_tf32(acc[fm][fn], af[fm], bf[fn]);
        }
    }

    // -------- epilogue: transpose via smem, bias+relu, coalesced stores --------
    __syncthreads();
    float* Dsh = sh;                                   // [128 n][DST]
#pragma unroll
    for (int fm = 0; fm < 4; fm++) {
        int m = (wm << 6) + (fm << 4) + g;
#pragma unroll
        for (int fn = 0; fn < 4; fn++) {
            int n = (wn << 5) + (fn << 3) + (t << 1);
            Dsh[n * DST + m]           = acc[fm][fn][0];
            Dsh[(n + 1) * DST + m]     = acc[fm][fn][1];
            Dsh[n * DST + m + 8]       = acc[fm][fn][2];
            Dsh[(n + 1) * DST + m + 8] = acc[fm][fn][3];
        }
    }
    __syncthreads();
    for (int i = tid; i < 4096; i += 256) {
        int n = i >> 5, cc = (i & 31) << 2;
        int pos = NB + n;
        if (pos < Npos) {
            float4 v = *reinterpret_cast<float4*>(&Dsh[n * DST + cc]);
            v.x = fmaxf(v.x + __ldg(&bias[M0 + cc + 0]), 0.f);
            v.y = fmaxf(v.y + __ldg(&bias[M0 + cc + 1]), 0.f);
            v.z = fmaxf(v.z + __ldg(&bias[M0 + cc + 2]), 0.f);
            v.w = fmaxf(v.w + __ldg(&bias[M0 + cc + 3]), 0.f);
            *reinterpret_cast<float4*>(outp + (bq + pos) * Cout + M0 + cc) = v;
        }
    }
}

// ---------------- pool1: g_c1 (34^3 pos-major) -> d_out l1 + g_l1pad ----------------
__global__ __launch_bounds__(128) void pool1_kernel(float* __restrict__ dout) {
    int pp = blockIdx.x;              // pooled pos in 16^3
    int b = blockIdx.z;
    int P0 = pp >> 8, P1 = (pp >> 4) & 15, P2 = pp & 15;
    int co4 = threadIdx.x << 2;

    float4 m = make_float4(-1e30f, -1e30f, -1e30f, -1e30f);
#pragma unroll
    for (int a = 0; a < 8; a++) {
        int c = (2 * P0 + (a >> 2) + 1) * (SP1 * SP1) + (2 * P1 + ((a >> 1) & 1) + 1) * SP1 + (2 * P2 + (a & 1) + 1);
        float4 v = *reinterpret_cast<const float4*>(&g_c1[((long)b * NPAD1 + c) * C1 + co4]);
        m.x = fmaxf(m.x, v.x); m.y = fmaxf(m.y, v.y); m.z = fmaxf(m.z, v.z); m.w = fmaxf(m.w, v.w);
    }
    int pad2 = (P0 + 1) * (SP2 * SP2) + (P1 + 1) * SP2 + (P2 + 1);
    *reinterpret_cast<float4*>(&g_l1pad[((long)b * NPAD2 + pad2) * C1 + co4]) = m;

    long ob = ((long)b * 1024 + co4) * 4096 + pp;
    dout[ob] = m.x; dout[ob + 4096] = m.y; dout[ob + 2 * 4096] = m.z; dout[ob + 3 * 4096] = m.w;
}

// ---------------- pool2: g_c2 (18^3 pos-major) -> g_l2 (chan-major 8^3) ----------------
__global__ __launch_bounds__(256) void pool2_kernel() {
    int pp = blockIdx.x;              // pooled pos in 8^3
    int b = blockIdx.z;
    int Q0 = pp >> 6, Q1 = (pp >> 3) & 7, Q2 = pp & 7;
    int co4 = threadIdx.x << 2;

    float4 m = make_float4(-1e30f, -1e30f, -1e30f, -1e30f);
#pragma unroll
    for (int a = 0; a < 8; a++) {
        int c = (2 * Q0 + (a >> 2) + 1) * (SP2 * SP2) + (2 * Q1 + ((a >> 1) & 1) + 1) * SP2 + (2 * Q2 + (a & 1) + 1);
        float4 v = *reinterpret_cast<const float4*>(&g_c2[((long)b * NPAD2 + c) * C2 + co4]);
        m.x = fmaxf(m.x, v.x); m.y = fmaxf(m.y, v.y); m.z = fmaxf(m.z, v.z); m.w = fmaxf(m.w, v.w);
    }
    long ob = ((long)b * 1024 + co4) * 512 + pp;
    g_l2[ob] = m.x; g_l2[ob + 512] = m.y; g_l2[ob + 2 * 512] = m.z; g_l2[ob + 3 * 512] = m.w;
}

// ---------------- convT: 8 parity GEMMs (FFMA) ----------------
__global__ __launch_bounds__(256) void convt_kernel(const float* __restrict__ bt, float* __restrict__ out) {
    __shared__ float w_sh[32 * 128];
    __shared__ float x_sh[32 * 64];
    int posT = blockIdx.x;
    int coT  = blockIdx.y;
    int bp   = blockIdx.z;
    int b = bp >> 3, par = bp & 7;
    int tid = threadIdx.x;
    int col = tid & 31, prow = tid >> 5;

    const float* wbase = g_WtT + (long)par * (1024 * 512);
    const float* xbase = g_l2 + (long)b * (C2 * 512);

    float acc[4][8];
#pragma unroll
    for (int jc = 0; jc < 4; jc++)
#pragma unroll
        for (int jp = 0; jp < 8; jp++) acc[jc][jp] = 0.0f;

    for (int ci0 = 0; ci0 < 1024; ci0 += 32) {
        __syncthreads();
        for (int idx = tid; idx < 32 * 128; idx += 256) {
            int k = idx >> 7, c = idx & 127;
            w_sh[idx] = wbase[(long)(ci0 + k) * 512 + coT * 128 + c];
        }
        for (int idx = tid; idx < 32 * 64; idx += 256) {
            int k = idx >> 6, p = idx & 63;
            x_sh[idx] = xbase[(long)(ci0 + k) * 512 + posT * 64 + p];
        }
        __syncthreads();
#pragma unroll 4
        for (int k = 0; k < 32; k++) {
            float xv[8], wv[4];
#pragma unroll
            for (int jp = 0; jp < 8; jp++) xv[jp] = x_sh[k * 64 + prow + 8 * jp];
#pragma unroll
            for (int jc = 0; jc < 4; jc++) wv[jc] = w_sh[k * 128 + col + 32 * jc];
#pragma unroll
            for (int jc = 0; jc < 4; jc++)
#pragma unroll
                for (int jp = 0; jp < 8; jp++) acc[jc][jp] = fmaf(wv[jc], xv[jp], acc[jc][jp]);
        }
    }

    int az = par >> 2, ay = (par >> 1) & 1, ax = par & 1;
#pragma unroll
    for (int jc = 0; jc < 4; jc++) {
        int co = coT * 128 + col + 32 * jc;
        float bv = __ldg(&bt[co]);
#pragma unroll
        for (int jp = 0; jp < 8; jp++) {
            int pos = posT * 64 + prow + 8 * jp;
            int iz = pos >> 6, iy = (pos >> 3) & 7, ix = pos & 7;
            int s = (2 * iz + az) * 256 + (2 * iy + ay) * 16 + (2 * ix + ax);
            out[((long)b * 1024 + 512 + co) * 4096 + s] = acc[jc][jp] + bv;
        }
    }
}

// ---------------- launcher ----------------
extern "C" void kernel_launch(void* const* d_in, const int* in_sizes, int n_in,
                              void* d_out, int out_size)
{
    const float* pc  = (const float*)d_in[0];
    const float* W1  = (const float*)d_in[1];
    const float* b1  = (const float*)d_in[2];
    const float* W2  = (const float*)d_in[3];
    const float* b2  = (const float*)d_in[4];
    const float* Wc1 = (const float*)d_in[5];
    const float* bc1 = (const float*)d_in[6];
    const float* Wc2 = (const float*)d_in[7];
    const float* bc2 = (const float*)d_in[8];
    const float* Wt  = (const float*)d_in[9];
    const float* bt  = (const float*)d_in[10];
    float* out = (float*)d_out;

    void *p_xpad, *p_wk1, *p_wk2, *p_c1, *p_l1pad, *p_c2;
    cudaGetSymbolAddress(&p_xpad, g_xpad);
    cudaGetSymbolAddress(&p_wk1, g_wk1);
    cudaGetSymbolAddress(&p_wk2, g_wk2);
    cudaGetSymbolAddress(&p_c1, g_c1);
    cudaGetSymbolAddress(&p_l1pad, g_l1pad);
    cudaGetSymbolAddress(&p_c2, g_c2);

    const int smem_pf = (128 * 257 + 128 * 65) * 4;           // 164,864 B
    const int smem_gm = 128 * DST * 4;                        // 67,584 B
    cudaFuncSetAttribute(point_f_scatter_kernel, cudaFuncAttributeMaxDynamicSharedMemorySize, smem_pf);
    cudaFuncSetAttribute(gemm_conv_mma, cudaFuncAttributeMaxDynamicSharedMemorySize, smem_gm);

    // 1. zero scatter targets (replay-safe)
    zero_scratch_kernel<<<2048, 256>>>();
    // 2. weight transposes
    wt_transpose_kernel<<<(8 * 1024 * 512 + 255) / 256, 256>>>(Wt);
    wk_transpose_kernel<<<4096, 256>>>(Wc1, (float*)p_wk1, C1, C0);
    wk_transpose_kernel<<<8192, 256>>>(Wc2, (float*)p_wk2, C2, C1);
    // 3. point MLP
    point_h_kernel<<<TOTPTS / 8, 256>>>(pc, W1, b1);
    point_f_scatter_kernel<<<TOTPTS / 64, 256, smem_pf>>>(W2, b2);
    // 4. conv1: tf32 mma GEMM over padded 34^3 positions
    gemm_conv_mma<<<dim3((NPAD1 + 127) / 128, C1 / 128, BATCH), 256, smem_gm>>>(
        (const float*)p_wk1, (const float*)p_xpad, bc1, (float*)p_c1, C0, 4, SP1, NPAD1, C1);
    // 5. pool1 -> d_out[:,0:512,:] and g_l1pad
    pool1_kernel<<<dim3(4096, 1, BATCH), 128>>>(out);
    // 6. conv2: tf32 mma GEMM over padded 18^3 positions
    gemm_conv_mma<<<dim3((NPAD2 + 127) / 128, C2 / 128, BATCH), 256, smem_gm>>>(
        (const float*)p_wk2, (const float*)p_l1pad, bc2, (float*)p_c2, C1, 5, SP2, NPAD2, C2);
    // 7. pool2 -> g_l2
    pool2_kernel<<<dim3(512, 1, BATCH), 256>>>();
    // 8. convT -> d_out[:,512:1024,:]
    convt_kernel<<<dim3(8, 4, 16), 256>>>(bt, out);
}

// round 7
// speedup vs baseline: 2.6563x; 1.2647x over previous
#include <cuda_runtime.h>
#include <cstdint>

// ---------------- problem constants ----------------
#define BATCH 2
#define NPTS 100000
#define TOTPTS (BATCH * NPTS)
#define C0 256
#define C1 512
#define C2 1024
#define SP1 34                 // padded 32+2
#define NPAD1 (SP1*SP1*SP1)    // 39304
#define SP2 18                 // padded 16+2
#define NPAD2 (SP2*SP2*SP2)    // 5832
#define STG 20                 // staging smem row stride (floats; conflict-free + 16B aligned rows)
#define DST 132                // epilogue smem row stride
#define STAGE_F (2 * 128 * STG)   // floats per stage (A+B) = 5120
#define BOFF_F (128 * STG)        // B offset within stage  = 2560

// ---------------- device scratch ----------------
__device__ float g_xpad[BATCH * NPAD1 * C0];     // conv1 input, pos-major (tf32-rounded)
__device__ float g_h[TOTPTS * 128];              // point hidden
__device__ int   g_flat[TOTPTS];                 // padded voxel index
__device__ float g_wk1[27 * C1 * C0];            // conv1 W [k][co][ci] (tf32)
__device__ float g_wk2[27 * C2 * C1];            // conv2 W [k][co][ci] (tf32)
__device__ float g_c1[BATCH * NPAD1 * C1];       // conv1 pre-pool pos-major (full fp32)
__device__ float g_l1pad[BATCH * NPAD2 * C1];    // pooled l1, pos-major (tf32-rounded)
__device__ float g_c2[BATCH * NPAD2 * C2];       // conv2 pre-pool pos-major
__device__ float g_l2[BATCH * C2 * 512];         // pooled l2, chan-major
__device__ float g_WtT[8 * 1024 * 512];          // convT W (par,ci,co)

// ---------------- helpers ----------------
__device__ __forceinline__ uint32_t smem_u32p(const void* p) {
    uint32_t a;
    asm("{ .reg .u64 t; cvta.to.shared.u64 t, %1; cvt.u32.u64 %0, t; }" : "=r"(a) : "l"(p));
    return a;
}
__device__ __forceinline__ uint32_t f2tf(float x) {
    uint32_t u;
    asm("cvt.rna.tf32.f32 %0, %1;" : "=r"(u) : "f"(x));
    return u;
}
__device__ __forceinline__ float f2tf_f(float x) { return __uint_as_float(f2tf(x)); }
__device__ __forceinline__ void mma_tf32(float* c, const uint32_t* a, const uint32_t* b) {
    asm volatile(
        "mma.sync.aligned.m16n8k8.row.col.f32.tf32.tf32.f32 "
        "{%0,%1,%2,%3}, {%4,%5,%6,%7}, {%8,%9}, {%0,%1,%2,%3};\n"
        : "+f"(c[0]), "+f"(c[1]), "+f"(c[2]), "+f"(c[3])
        : "r"(a[0]), "r"(a[1]), "r"(a[2]), "r"(a[3]), "r"(b[0]), "r"(b[1]));
}
#define CP_ASYNC16(sa, ga, sz) \
    asm volatile("cp.async.cg.shared.global [%0], [%1], 16, %2;" :: "r"(sa), "l"(ga), "r"(sz) : "memory")
#define CP_COMMIT() asm volatile("cp.async.commit_group;" ::: "memory")
#define CP_WAIT2()  asm volatile("cp.async.wait_group 2;" ::: "memory")
#define CP_WAITALL() asm volatile("cp.async.wait_all;" ::: "memory")

// ---------------- zero scratch (replay-safe) ----------------
__global__ void zero_scratch_kernel() {
    float4* p1 = reinterpret_cast<float4*>(g_xpad);
    int n1 = (BATCH * NPAD1 * C0) / 4;
    for (int i = blockIdx.x * blockDim.x + threadIdx.x; i < n1; i += gridDim.x * blockDim.x)
        p1[i] = make_float4(0.f, 0.f, 0.f, 0.f);
    float4* p2 = reinterpret_cast<float4*>(g_l1pad);
    int n2 = (BATCH * NPAD2 * C1) / 4;
    for (int i = blockIdx.x * blockDim.x + threadIdx.x; i < n2; i += gridDim.x * blockDim.x)
        p2[i] = make_float4(0.f, 0.f, 0.f, 0.f);
}

// ---------------- conv weight transpose [co][ci][27] -> [k][co][ci], tf32-round ----------------
__global__ void wk_transpose_kernel(const float* __restrict__ w, float* __restrict__ wk, int Cout, int Cin) {
    long total = (long)27 * Cout * Cin;
    for (long i = (long)blockIdx.x * blockDim.x + threadIdx.x; i < total; i += (long)gridDim.x * blockDim.x) {
        int ci = (int)(i % Cin);
        long r = i / Cin;
        int co = (int)(r % Cout);
        int k  = (int)(r / Cout);
        wk[i] = f2tf_f(w[((long)co * Cin + ci) * 27 + k]);
    }
}

// ---------------- convT weight transpose (1024,512,2,2,2) -> (par,ci,co) ----------------
__global__ void wt_transpose_kernel(const float* __restrict__ Wt) {
    int i = blockIdx.x * blockDim.x + threadIdx.x;
    if (i >= 8 * 1024 * 512) return;
    int co = i & 511;
    int ci = (i >> 9) & 1023;
    int par = i >> 19;
    g_WtT[i] = Wt[ci * 4096 + co * 8 + par];
}

// ---------------- point MLP stage 1 ----------------
__global__ __launch_bounds__(256) void point_h_kernel(
    const float* __restrict__ pc, const float* __restrict__ W1, const float* __restrict__ b1)
{
    __shared__ float W1s[384];
    __shared__ float b1s[128];
    int tid = threadIdx.x;
    for (int i = tid; i < 384; i += 256) W1s[i] = W1[i];
    if (tid < 128) b1s[tid] = b1[tid];
    __syncthreads();

    int P = blockIdx.x * 8 + (tid >> 5);
    int lane = tid & 31;
    if (P >= TOTPTS) return;

    float x = pc[P * 3 + 0], y = pc[P * 3 + 1], z = pc[P * 3 + 2];
    int ix = (int)floorf((x + 1.0f) * 16.0f);
    int iy = (int)floorf((y + 1.0f) * 16.0f);
    int iz = (int)floorf((z + 1.0f) * 16.0f);
    float xcx = x - (ix * 0.0625f + 0.03125f - 1.0f);
    float xcy = y - (iy * 0.0625f + 0.03125f - 1.0f);
    float xcz = z - (iz * 0.0625f + 0.03125f - 1.0f);

    if (lane == 0) g_flat[P] = (ix + 1) * (SP1 * SP1) + (iy + 1) * SP1 + (iz + 1);  // padded pos

    float* hrow = g_h + (long)P * 128;
#pragma unroll
    for (int j = 0; j < 4; j++) {
        int o = lane + 32 * j;
        float v = W1s[o * 3 + 0] * xcx + W1s[o * 3 + 1] * xcy + W1s[o * 3 + 2] * xcz + b1s[o];
        hrow[o] = fmaxf(v, 0.0f);
    }
}

// ---------------- point MLP stage 2 + tf32-rounded scatter-max ----------------
__global__ __launch_bounds__(256) void point_f_scatter_kernel(
    const float* __restrict__ W2, const float* __restrict__ b2)
{
    extern __shared__ float sm[];
    float* W2s = sm;                 // [k][o] stride 257
    float* hs  = sm + 128 * 257;     // [k][p] stride 65
    int tid = threadIdx.x;
    int P0 = blockIdx.x * 64;

    for (int idx = tid; idx < 256 * 128; idx += 256) {
        int o = idx >> 7, k = idx & 127;
        W2s[k * 257 + o] = W2[idx];
    }
    const float* hsrc = g_h + (long)P0 * 128;
    for (int idx = tid; idx < 64 * 128; idx += 256) {
        int p = idx >> 7, k = idx & 127;
        hs[k * 65 + p] = hsrc[idx];
    }
    __syncthreads();

    int cg = tid & 31;
    int pg = tid >> 5;
    float acc[8][8];
#pragma unroll
    for (int i = 0; i < 8; i++)
#pragma unroll
        for (int j = 0; j < 8; j++) acc[i][j] = 0.0f;

#pragma unroll 4
    for (int k = 0; k < 128; k++) {
        float hv[8], wv[8];
#pragma unroll
        for (int i = 0; i < 8; i++) hv[i] = hs[k * 65 + pg * 8 + i];
#pragma unroll
        for (int j = 0; j < 8; j++) wv[j] = W2s[k * 257 + cg + 32 * j];
#pragma unroll
        for (int i = 0; i < 8; i++)
#pragma unroll
            for (int j = 0; j < 8; j++) acc[i][j] = fmaf(hv[i], wv[j], acc[i][j]);
    }

    float bv[8];
#pragma unroll
    for (int j = 0; j < 8; j++) bv[j] = __ldg(&b2[cg + 32 * j]);

    int* gx = reinterpret_cast<int*>(g_xpad);
#pragma unroll
    for (int i = 0; i < 8; i++) {
        int P = P0 + pg * 8 + i;
        int b = P / NPTS;
        long base = ((long)b * NPAD1 + g_flat[P]) * C0;
#pragma unroll
        for (int j = 0; j < 8; j++) {
            float f = f2tf_f(acc[i][j] + bv[j]);   // pre-round: g_xpad is GEMM input only
            if (f > 0.0f)
                atomicMax(&gx[base + cg + 32 * j], __float_as_int(f));
        }
    }
}

// ---------------- tf32 mma.sync implicit-GEMM conv3x3x3 (+bias+relu) ----------------
// CTA: M=128 co x N=128 positions; K = 27 taps x Cin in 16-ci chunks.
// 4-stage cp.async pipeline; 8 warps 2(M)x4(N); warp tile 64x32 via m16n8k8.
__global__ __launch_bounds__(256, 2) void gemm_conv_mma(
    const float* __restrict__ wk,     // [27][Cout][Cin]  tf32-rounded
    const float* __restrict__ xp,     // [b][Npos][Cin]   tf32-rounded, zero-padded borders
    const float* __restrict__ bias,
    float* __restrict__ outp,         // [b][Npos][Cout] pre-pool, pos-major
    int Cin, int ncShift, int Sp, int Npos, int Cout)
{
    extern __shared__ float sh[];
    uint32_t sbase = smem_u32p(sh);

    int tid = threadIdx.x;
    int lane = tid & 31, wid = tid >> 5;
    int g = lane >> 2, t = lane & 3;
    int wm = wid >> 2, wn = wid & 3;
    int NB = blockIdx.x << 7;
    int M0 = blockIdx.y << 7;
    long bq = (long)blockIdx.z * Npos;
    int total = 27 << ncShift;
    int ncMask = (1 << ncShift) - 1;

    int rowL = tid >> 2;              // 0..63 (+64 for q=1)
    int c4 = (tid & 3) << 2;          // ci sub-offset (float units)

    float acc[4][4][4];
#pragma unroll
    for (int fm = 0; fm < 4; fm++)
#pragma unroll
        for (int fn = 0; fn < 4; fn++)
#pragma unroll
            for (int r = 0; r < 4; r++) acc[fm][fn][r] = 0.0f;

    auto issue_chunk = [&](int c) {
        int stg = c & 3;
        int tap = c >> ncShift;
        int ci0 = (c & ncMask) << 4;
        int k0 = tap / 9; int rr = tap - 9 * k0; int k1 = rr / 3; int k2 = rr - 3 * k1;
        int drow = (k0 - 1) * Sp * Sp + (k1 - 1) * Sp + (k2 - 1);
        uint32_t stb = sbase + (uint32_t)stg * (STAGE_F * 4);
#pragma unroll
        for (int q = 0; q < 2; q++) {
            int row = rowL + (q << 6);
            uint32_t saA = stb + ((uint32_t)row * STG + c4) * 4;
            const float* gaA = wk + ((long)tap * Cout + M0 + row) * Cin + ci0 + c4;
            CP_ASYNC16(saA, gaA, 16);
            int gpos = NB + drow + row;
            uint32_t saB = stb + (uint32_t)(BOFF_F + row * STG + c4) * 4;
            int ok = ((unsigned)gpos < (unsigned)Npos) ? 16 : 0;
            int gp = gpos < 0 ? 0 : (gpos >= Npos ? Npos - 1 : gpos);
            const float* gaB = xp + (bq + gp) * Cin + ci0 + c4;
            CP_ASYNC16(saB, gaB, ok);
        }
        CP_COMMIT();
    };

    // prologue: 3 chunks in flight
    issue_chunk(0); issue_chunk(1); issue_chunk(2);

    for (int c = 0; c < total; c++) {
        CP_WAIT2();            // chunk c's group retired (empty tail groups keep count exact)
        __syncthreads();       // all threads' stage-c data visible; stage (c+3)&3 free
        if (c + 3 < total) issue_chunk(c + 3); else CP_COMMIT();

        const uint32_t* As = reinterpret_cast<const uint32_t*>(sh) + (c & 3) * STAGE_F;
        const uint32_t* Bs = As + BOFF_F;
#pragma unroll
        for (int ks = 0; ks < 2; ks++) {
            uint32_t af[4][4], bf[4][2];
            int kc = (ks << 3) + t;
#pragma unroll
            for (int fm = 0; fm < 4; fm++) {
                int r0 = (wm << 6) + (fm << 4) + g;
                af[fm][0] = As[r0 * STG + kc];
                af[fm][1] = As[(r0 + 8) * STG + kc];
                af[fm][2] = As[r0 * STG + kc + 4];
                af[fm][3] = As[(r0 + 8) * STG + kc + 4];
            }
#pragma unroll
            for (int fn = 0; fn < 4; fn++) {
                int n0 = (wn << 5) + (fn << 3) + g;
                bf[fn][0] = Bs[n0 * STG + kc];
                bf[fn][1] = Bs[n0 * STG + kc + 4];
            }
#pragma unroll
            for (int fm = 0; fm < 4; fm++)
#pragma unroll
                for (int fn = 0; fn < 4; fn++)
                    mma_tf32(acc[fm][fn], af[fm], bf[fn]);
        }
    }
    CP_WAITALL();

    // -------- epilogue: transpose via smem, bias+relu, coalesced stores --------
    __syncthreads();
    float* Dsh = sh;                                   // [128 n][DST]
#pragma unroll
    for (int fm = 0; fm < 4; fm++) {
        int m = (wm << 6) + (fm << 4) + g;
#pragma unroll
        for (int fn = 0; fn < 4; fn++) {
            int n = (wn << 5) + (fn << 3) + (t << 1);
            Dsh[n * DST + m]           = acc[fm][fn][0];
            Dsh[(n + 1) * DST + m]     = acc[fm][fn][1];
            Dsh[n * DST + m + 8]       = acc[fm][fn][2];
            Dsh[(n + 1) * DST + m + 8] = acc[fm][fn][3];
        }
    }
    __syncthreads();
    for (int i = tid; i < 4096; i += 256) {
        int n = i >> 5, cc = (i & 31) << 2;
        int pos = NB + n;
        if (pos < Npos) {
            float4 v = *reinterpret_cast<float4*>(&Dsh[n * DST + cc]);
            v.x = fmaxf(v.x + __ldg(&bias[M0 + cc + 0]), 0.f);
            v.y = fmaxf(v.y + __ldg(&bias[M0 + cc + 1]), 0.f);
            v.z = fmaxf(v.z + __ldg(&bias[M0 + cc + 2]), 0.f);
            v.w = fmaxf(v.w + __ldg(&bias[M0 + cc + 3]), 0.f);
            *reinterpret_cast<float4*>(outp + (bq + pos) * Cout + M0 + cc) = v;
        }
    }
}

// ---------------- pool1: g_c1 (34^3 pos-major) -> d_out l1 (fp32) + g_l1pad (tf32) ----------------
__global__ __launch_bounds__(128) void pool1_kernel(float* __restrict__ dout) {
    int pp = blockIdx.x;              // pooled pos in 16^3
    int b = blockIdx.z;
    int P0 = pp >> 8, P1 = (pp >> 4) & 15, P2 = pp & 15;
    int co4 = threadIdx.x << 2;

    float4 m = make_float4(-1e30f, -1e30f, -1e30f, -1e30f);
#pragma unroll
    for (int a = 0; a < 8; a++) {
        int c = (2 * P0 + (a >> 2) + 1) * (SP1 * SP1) + (2 * P1 + ((a >> 1) & 1) + 1) * SP1 + (2 * P2 + (a & 1) + 1);
        float4 v = *reinterpret_cast<const float4*>(&g_c1[((long)b * NPAD1 + c) * C1 + co4]);
        m.x = fmaxf(m.x, v.x); m.y = fmaxf(m.y, v.y); m.z = fmaxf(m.z, v.z); m.w = fmaxf(m.w, v.w);
    }
    int pad2 = (P0 + 1) * (SP2 * SP2) + (P1 + 1) * SP2 + (P2 + 1);
    float4 mt = make_float4(f2tf_f(m.x), f2tf_f(m.y), f2tf_f(m.z), f2tf_f(m.w));
    *reinterpret_cast<float4*>(&g_l1pad[((long)b * NPAD2 + pad2) * C1 + co4]) = mt;

    long ob = ((long)b * 1024 + co4) * 4096 + pp;
    dout[ob] = m.x; dout[ob + 4096] = m.y; dout[ob + 2 * 4096] = m.z; dout[ob + 3 * 4096] = m.w;
}

// ---------------- pool2: g_c2 (18^3 pos-major) -> g_l2 (chan-major 8^3) ----------------
__global__ __launch_bounds__(256) void pool2_kernel() {
    int pp = blockIdx.x;              // pooled pos in 8^3
    int b = blockIdx.z;
    int Q0 = pp >> 6, Q1 = (pp >> 3) & 7, Q2 = pp & 7;
    int co4 = threadIdx.x << 2;

    float4 m = make_float4(-1e30f, -1e30f, -1e30f, -1e30f);
#pragma unroll
    for (int a = 0; a < 8; a++) {
        int c = (2 * Q0 + (a >> 2) + 1) * (SP2 * SP2) + (2 * Q1 + ((a >> 1) & 1) + 1) * SP2 + (2 * Q2 + (a & 1) + 1);
        float4 v = *reinterpret_cast<const float4*>(&g_c2[((long)b * NPAD2 + c) * C2 + co4]);
        m.x = fmaxf(m.x, v.x); m.y = fmaxf(m.y, v.y); m.z = fmaxf(m.z, v.z); m.w = fmaxf(m.w, v.w);
    }
    long ob = ((long)b * 1024 + co4) * 512 + pp;
    g_l2[ob] = m.x; g_l2[ob + 512] = m.y; g_l2[ob + 2 * 512] = m.z; g_l2[ob + 3 * 512] = m.w;
}

// ---------------- convT: 8 parity GEMMs (FFMA) ----------------
__global__ __launch_bounds__(256) void convt_kernel(const float* __restrict__ bt, float* __restrict__ out) {
    __shared__ float w_sh[32 * 128];
    __shared__ float x_sh[32 * 64];
    int posT = blockIdx.x;
    int coT  = blockIdx.y;
    int bp   = blockIdx.z;
    int b = bp >> 3, par = bp & 7;
    int tid = threadIdx.x;
    int col = tid & 31, prow = tid >> 5;

    const float* wbase = g_WtT + (long)par * (1024 * 512);
    const float* xbase = g_l2 + (long)b * (C2 * 512);

    float acc[4][8];
#pragma unroll
    for (int jc = 0; jc < 4; jc++)
#pragma unroll
        for (int jp = 0; jp < 8; jp++) acc[jc][jp] = 0.0f;

    for (int ci0 = 0; ci0 < 1024; ci0 += 32) {
        __syncthreads();
        for (int idx = tid; idx < 32 * 128; idx += 256) {
            int k = idx >> 7, c = idx & 127;
            w_sh[idx] = wbase[(long)(ci0 + k) * 512 + coT * 128 + c];
        }
        for (int idx = tid; idx < 32 * 64; idx += 256) {
            int k = idx >> 6, p = idx & 63;
            x_sh[idx] = xbase[(long)(ci0 + k) * 512 + posT * 64 + p];
        }
        __syncthreads();
#pragma unroll 4
        for (int k = 0; k < 32; k++) {
            float xv[8], wv[4];
#pragma unroll
            for (int jp = 0; jp < 8; jp++) xv[jp] = x_sh[k * 64 + prow + 8 * jp];
#pragma unroll
            for (int jc = 0; jc < 4; jc++) wv[jc] = w_sh[k * 128 + col + 32 * jc];
#pragma unroll
            for (int jc = 0; jc < 4; jc++)
#pragma unroll
                for (int jp = 0; jp < 8; jp++) acc[jc][jp] = fmaf(wv[jc], xv[jp], acc[jc][jp]);
        }
    }

    int az = par >> 2, ay = (par >> 1) & 1, ax = par & 1;
#pragma unroll
    for (int jc = 0; jc < 4; jc++) {
        int co = coT * 128 + col + 32 * jc;
        float bv = __ldg(&bt[co]);
#pragma unroll
        for (int jp = 0; jp < 8; jp++) {
            int pos = posT * 64 + prow + 8 * jp;
            int iz = pos >> 6, iy = (pos >> 3) & 7, ix = pos & 7;
            int s = (2 * iz + az) * 256 + (2 * iy + ay) * 16 + (2 * ix + ax);
            out[((long)b * 1024 + 512 + co) * 4096 + s] = acc[jc][jp] + bv;
        }
    }
}

// ---------------- launcher ----------------
extern "C" void kernel_launch(void* const* d_in, const int* in_sizes, int n_in,
                              void* d_out, int out_size)
{
    const float* pc  = (const float*)d_in[0];
    const float* W1  = (const float*)d_in[1];
    const float* b1  = (const float*)d_in[2];
    const float* W2  = (const float*)d_in[3];
    const float* b2  = (const float*)d_in[4];
    const float* Wc1 = (const float*)d_in[5];
    const float* bc1 = (const float*)d_in[6];
    const float* Wc2 = (const float*)d_in[7];
    const float* bc2 = (const float*)d_in[8];
    const float* Wt  = (const float*)d_in[9];
    const float* bt  = (const float*)d_in[10];
    float* out = (float*)d_out;

    void *p_xpad, *p_wk1, *p_wk2, *p_c1, *p_l1pad, *p_c2;
    cudaGetSymbolAddress(&p_xpad, g_xpad);
    cudaGetSymbolAddress(&p_wk1, g_wk1);
    cudaGetSymbolAddress(&p_wk2, g_wk2);
    cudaGetSymbolAddress(&p_c1, g_c1);
    cudaGetSymbolAddress(&p_l1pad, g_l1pad);
    cudaGetSymbolAddress(&p_c2, g_c2);

    const int smem_pf = (128 * 257 + 128 * 65) * 4;           // 164,864 B
    const int smem_gm = 4 * STAGE_F * 4;                      // 81,920 B (>= epilogue 67,584)
    cudaFuncSetAttribute(point_f_scatter_kernel, cudaFuncAttributeMaxDynamicSharedMemorySize, smem_pf);
    cudaFuncSetAttribute(gemm_conv_mma, cudaFuncAttributeMaxDynamicSharedMemorySize, smem_gm);

    // 1. zero scatter targets (replay-safe)
    zero_scratch_kernel<<<2048, 256>>>();
    // 2. weight transposes (conv weights tf32-rounded)
    wt_transpose_kernel<<<(8 * 1024 * 512 + 255) / 256, 256>>>(Wt);
    wk_transpose_kernel<<<4096, 256>>>(Wc1, (float*)p_wk1, C1, C0);
    wk_transpose_kernel<<<8192, 256>>>(Wc2, (float*)p_wk2, C2, C1);
    // 3. point MLP
    point_h_kernel<<<TOTPTS / 8, 256>>>(pc, W1, b1);
    point_f_scatter_kernel<<<TOTPTS / 64, 256, smem_pf>>>(W2, b2);
    // 4. conv1: tf32 mma GEMM over padded 34^3 positions
    gemm_conv_mma<<<dim3((NPAD1 + 127) / 128, C1 / 128, BATCH), 256, smem_gm>>>(
        (const float*)p_wk1, (const float*)p_xpad, bc1, (float*)p_c1, C0, 4, SP1, NPAD1, C1);
    // 5. pool1 -> d_out[:,0:512,:] (fp32) and g_l1pad (tf32)
    pool1_kernel<<<dim3(4096, 1, BATCH), 128>>>(out);
    // 6. conv2: tf32 mma GEMM over padded 18^3 positions
    gemm_conv_mma<<<dim3((NPAD2 + 127) / 128, C2 / 128, BATCH), 256, smem_gm>>>(
        (const float*)p_wk2, (const float*)p_l1pad, bc2, (float*)p_c2, C1, 5, SP2, NPAD2, C2);
    // 7. pool2 -> g_l2
    pool2_kernel<<<dim3(512, 1, BATCH), 256>>>();
    // 8. convT -> d_out[:,512:1024,:]
    convt_kernel<<<dim3(8, 4, 16), 256>>>(bt, out);
}

// round 8
// speedup vs baseline: 4.8180x; 1.8138x over previous
#include <cuda_runtime.h>
#include <cuda_fp16.h>
#include <cstdint>

// ---------------- problem constants ----------------
#define BATCH 2
#define NPTS 100000
#define TOTPTS (BATCH * NPTS)
#define C0 256
#define C1 512
#define C2 1024
#define SP1 34                 // padded 32+2
#define NPAD1 (SP1*SP1*SP1)    // 39304
#define SP2 18                 // padded 16+2
#define NPAD2 (SP2*SP2*SP2)    // 5832
#define DST 132                // epilogue smem row stride (floats)
#define SROW 48                // staging smem row stride in BYTES (24 halves)
#define STAGE_B 12288          // bytes per stage: A 6144 + B 6144
#define B_OFF 6144

// ---------------- device scratch ----------------
__device__ float  g_xpad[BATCH * NPAD1 * C0];    // fp32 scatter grid (atomics)
__device__ __half g_xh[BATCH * NPAD1 * C0];      // fp16 conv1 input
__device__ float  g_h[TOTPTS * 128];             // point hidden
__device__ int    g_flat[TOTPTS];                // padded voxel index
__device__ __half g_wk1[27 * C1 * C0];           // conv1 W [k][co][ci] fp16
__device__ __half g_wk2[27 * C2 * C1];           // conv2 W [k][co][ci] fp16
__device__ float  g_c1[BATCH * NPAD1 * C1];      // conv1 pre-pool pos-major fp32
__device__ __half g_l1h[BATCH * NPAD2 * C1];     // pooled l1, pos-major fp16
__device__ float  g_c2[BATCH * NPAD2 * C2];      // conv2 pre-pool pos-major fp32
__device__ float  g_l2[BATCH * C2 * 512];        // pooled l2, chan-major
__device__ float  g_WtT[8 * 1024 * 512];         // convT W (par,ci,co)

// ---------------- helpers ----------------
__device__ __forceinline__ uint32_t smem_u32p(const void* p) {
    uint32_t a;
    asm("{ .reg .u64 t; cvta.to.shared.u64 t, %1; cvt.u32.u64 %0, t; }" : "=r"(a) : "l"(p));
    return a;
}
__device__ __forceinline__ void mma_f16(float* c, const uint32_t* a, const uint32_t* b) {
    asm volatile(
        "mma.sync.aligned.m16n8k16.row.col.f32.f16.f16.f32 "
        "{%0,%1,%2,%3}, {%4,%5,%6,%7}, {%8,%9}, {%0,%1,%2,%3};\n"
        : "+f"(c[0]), "+f"(c[1]), "+f"(c[2]), "+f"(c[3])
        : "r"(a[0]), "r"(a[1]), "r"(a[2]), "r"(a[3]), "r"(b[0]), "r"(b[1]));
}
#define LDSM_X4(r0, r1, r2, r3, addr) \
    asm volatile("ldmatrix.sync.aligned.m8n8.x4.shared.b16 {%0,%1,%2,%3}, [%4];" \
        : "=r"(r0), "=r"(r1), "=r"(r2), "=r"(r3) : "r"(addr))
#define CP_ASYNC16(sa, ga, sz) \
    asm volatile("cp.async.cg.shared.global [%0], [%1], 16, %2;" :: "r"(sa), "l"(ga), "r"(sz) : "memory")
#define CP_COMMIT() asm volatile("cp.async.commit_group;" ::: "memory")
#define CP_WAIT2()  asm volatile("cp.async.wait_group 2;" ::: "memory")
#define CP_WAITALL() asm volatile("cp.async.wait_all;" ::: "memory")

// ---------------- zero scratch (replay-safe) ----------------
__global__ void zero_scratch_kernel() {
    float4* p1 = reinterpret_cast<float4*>(g_xpad);
    int n1 = (BATCH * NPAD1 * C0) / 4;
    for (int i = blockIdx.x * blockDim.x + threadIdx.x; i < n1; i += gridDim.x * blockDim.x)
        p1[i] = make_float4(0.f, 0.f, 0.f, 0.f);
    float4* p2 = reinterpret_cast<float4*>(g_l1h);
    int n2 = (BATCH * NPAD2 * C1) / 8;     // halves, 8 per float4
    for (int i = blockIdx.x * blockDim.x + threadIdx.x; i < n2; i += gridDim.x * blockDim.x)
        p2[i] = make_float4(0.f, 0.f, 0.f, 0.f);
}

// ---------------- pack fp32 grid -> fp16 ----------------
__global__ void pack_half_kernel(const float* __restrict__ src, __half* __restrict__ dst, long n4) {
    for (long i = (long)blockIdx.x * blockDim.x + threadIdx.x; i < n4; i += (long)gridDim.x * blockDim.x) {
        float4 v = reinterpret_cast<const float4*>(src)[i];
        __half2* d = reinterpret_cast<__half2*>(dst) + 2 * i;
        d[0] = __floats2half2_rn(v.x, v.y);
        d[1] = __floats2half2_rn(v.z, v.w);
    }
}

// ---------------- conv weight transpose [co][ci][27] -> [k][co][ci] fp16 ----------------
__global__ void wk_transpose_kernel(const float* __restrict__ w, __half* __restrict__ wk, int Cout, int Cin) {
    long total = (long)27 * Cout * Cin;
    for (long i = (long)blockIdx.x * blockDim.x + threadIdx.x; i < total; i += (long)gridDim.x * blockDim.x) {
        int ci = (int)(i % Cin);
        long r = i / Cin;
        int co = (int)(r % Cout);
        int k  = (int)(r / Cout);
        wk[i] = __float2half_rn(w[((long)co * Cin + ci) * 27 + k]);
    }
}

// ---------------- convT weight transpose (1024,512,2,2,2) -> (par,ci,co) ----------------
__global__ void wt_transpose_kernel(const float* __restrict__ Wt) {
    int i = blockIdx.x * blockDim.x + threadIdx.x;
    if (i >= 8 * 1024 * 512) return;
    int co = i & 511;
    int ci = (i >> 9) & 1023;
    int par = i >> 19;
    g_WtT[i] = Wt[ci * 4096 + co * 8 + par];
}

// ---------------- point MLP stage 1 ----------------
__global__ __launch_bounds__(256) void point_h_kernel(
    const float* __restrict__ pc, const float* __restrict__ W1, const float* __restrict__ b1)
{
    __shared__ float W1s[384];
    __shared__ float b1s[128];
    int tid = threadIdx.x;
    for (int i = tid; i < 384; i += 256) W1s[i] = W1[i];
    if (tid < 128) b1s[tid] = b1[tid];
    __syncthreads();

    int P = blockIdx.x * 8 + (tid >> 5);
    int lane = tid & 31;
    if (P >= TOTPTS) return;

    float x = pc[P * 3 + 0], y = pc[P * 3 + 1], z = pc[P * 3 + 2];
    int ix = (int)floorf((x + 1.0f) * 16.0f);
    int iy = (int)floorf((y + 1.0f) * 16.0f);
    int iz = (int)floorf((z + 1.0f) * 16.0f);
    float xcx = x - (ix * 0.0625f + 0.03125f - 1.0f);
    float xcy = y - (iy * 0.0625f + 0.03125f - 1.0f);
    float xcz = z - (iz * 0.0625f + 0.03125f - 1.0f);

    if (lane == 0) g_flat[P] = (ix + 1) * (SP1 * SP1) + (iy + 1) * SP1 + (iz + 1);  // padded pos

    float* hrow = g_h + (long)P * 128;
#pragma unroll
    for (int j = 0; j < 4; j++) {
        int o = lane + 32 * j;
        float v = W1s[o * 3 + 0] * xcx + W1s[o * 3 + 1] * xcy + W1s[o * 3 + 2] * xcz + b1s[o];
        hrow[o] = fmaxf(v, 0.0f);
    }
}

// ---------------- point MLP stage 2 + scatter-max (fp32 atomics) ----------------
__global__ __launch_bounds__(256) void point_f_scatter_kernel(
    const float* __restrict__ W2, const float* __restrict__ b2)
{
    extern __shared__ float sm[];
    float* W2s = sm;                 // [k][o] stride 257
    float* hs  = sm + 128 * 257;     // [k][p] stride 65
    int tid = threadIdx.x;
    int P0 = blockIdx.x * 64;

    for (int idx = tid; idx < 256 * 128; idx += 256) {
        int o = idx >> 7, k = idx & 127;
        W2s[k * 257 + o] = W2[idx];
    }
    const float* hsrc = g_h + (long)P0 * 128;
    for (int idx = tid; idx < 64 * 128; idx += 256) {
        int p = idx >> 7, k = idx & 127;
        hs[k * 65 + p] = hsrc[idx];
    }
    __syncthreads();

    int cg = tid & 31;
    int pg = tid >> 5;
    float acc[8][8];
#pragma unroll
    for (int i = 0; i < 8; i++)
#pragma unroll
        for (int j = 0; j < 8; j++) acc[i][j] = 0.0f;

#pragma unroll 4
    for (int k = 0; k < 128; k++) {
        float hv[8], wv[8];
#pragma unroll
        for (int i = 0; i < 8; i++) hv[i] = hs[k * 65 + pg * 8 + i];
#pragma unroll
        for (int j = 0; j < 8; j++) wv[j] = W2s[k * 257 + cg + 32 * j];
#pragma unroll
        for (int i = 0; i < 8; i++)
#pragma unroll
            for (int j = 0; j < 8; j++) acc[i][j] = fmaf(hv[i], wv[j], acc[i][j]);
    }

    float bv[8];
#pragma unroll
    for (int j = 0; j < 8; j++) bv[j] = __ldg(&b2[cg + 32 * j]);

    int* gx = reinterpret_cast<int*>(g_xpad);
#pragma unroll
    for (int i = 0; i < 8; i++) {
        int P = P0 + pg * 8 + i;
        int b = P / NPTS;
        long base = ((long)b * NPAD1 + g_flat[P]) * C0;
#pragma unroll
        for (int j = 0; j < 8; j++) {
            float f = acc[i][j] + bv[j];
            if (f > 0.0f)
                atomicMax(&gx[base + cg + 32 * j], __float_as_int(f));
        }
    }
}

// ---------------- fp16 mma.sync implicit-GEMM conv3x3x3 (+bias+relu) ----------------
// CTA: M=128 co x N=128 positions; K = 27 taps x Cin in 16-ci chunks (one m16n8k16 per chunk-step).
// 4-stage cp.async pipeline; ldmatrix.x4 fragment loads; 8 warps 2(M)x4(N).
__global__ __launch_bounds__(256, 2) void gemm_conv_h(
    const __half* __restrict__ wk,    // [27][Cout][Cin] fp16
    const __half* __restrict__ xp,    // [b][Npos][Cin]  fp16, zero-padded borders
    const float* __restrict__ bias,
    float* __restrict__ outp,         // [b][Npos][Cout] pre-pool, pos-major fp32
    int Cin, int ncShift, int Sp, int Npos, int Cout, int nbase)
{
    extern __shared__ float sh[];
    uint32_t sbase = smem_u32p(sh);

    int tid = threadIdx.x;
    int lane = tid & 31, wid = tid >> 5;
    int wm = wid >> 2, wn = wid & 3;
    int NB = nbase + (blockIdx.x << 7);
    int M0 = blockIdx.y << 7;
    long bq = (long)blockIdx.z * Npos;
    int total = 27 << ncShift;
    int ncMask = (1 << ncShift) - 1;
    int rowL = tid >> 1, seg = tid & 1;   // cp.async: row 0..127, 16B segment 0/1

    // ldmatrix per-lane byte offsets (within a stage)
    uint32_t ofsA[4], ofsB[2];
#pragma unroll
    for (int fm = 0; fm < 4; fm++)
        ofsA[fm] = (uint32_t)(((wm << 6) + (fm << 4) + (lane & 15)) * SROW + ((lane >> 4) << 4));
#pragma unroll
    for (int j = 0; j < 2; j++) {
        int row = (wn << 5) + (j << 4) + (lane & 7) + ((lane >> 4) << 3);
        ofsB[j] = (uint32_t)(B_OFF + row * SROW + (((lane >> 3) & 1) << 4));
    }

    float acc[4][4][4];
#pragma unroll
    for (int fm = 0; fm < 4; fm++)
#pragma unroll
        for (int fn = 0; fn < 4; fn++)
#pragma unroll
            for (int r = 0; r < 4; r++) acc[fm][fn][r] = 0.0f;

    auto issue_chunk = [&](int c) {
        int stg = c & 3;
        int tap = c >> ncShift;
        int ci0 = (c & ncMask) << 4;
        int k0 = tap / 9; int rr = tap - 9 * k0; int k1 = rr / 3; int k2 = rr - 3 * k1;
        int drow = (k0 - 1) * Sp * Sp + (k1 - 1) * Sp + (k2 - 1);
        uint32_t stb = sbase + (uint32_t)stg * STAGE_B;
        uint32_t sa = stb + (uint32_t)rowL * SROW + (seg << 4);
        const __half* ga = wk + ((long)tap * Cout + M0 + rowL) * Cin + ci0 + (seg << 3);
        CP_ASYNC16(sa, ga, 16);
        int gpos = NB + drow + rowL;
        uint32_t sb = stb + B_OFF + (uint32_t)rowL * SROW + (seg << 4);
        int ok = ((unsigned)gpos < (unsigned)Npos) ? 16 : 0;
        int gp = gpos < 0 ? 0 : (gpos >= Npos ? Npos - 1 : gpos);
        const __half* gb = xp + (bq + gp) * Cin + ci0 + (seg << 3);
        CP_ASYNC16(sb, gb, ok);
        CP_COMMIT();
    };

    issue_chunk(0); issue_chunk(1); issue_chunk(2);

    for (int c = 0; c < total; c++) {
        CP_WAIT2();
        __syncthreads();
        if (c + 3 < total) issue_chunk(c + 3); else CP_COMMIT();

        uint32_t stb = sbase + (uint32_t)(c & 3) * STAGE_B;
        uint32_t af[4][4], bf[2][4];
#pragma unroll
        for (int fm = 0; fm < 4; fm++)
            LDSM_X4(af[fm][0], af[fm][1], af[fm][2], af[fm][3], stb + ofsA[fm]);
#pragma unroll
        for (int j = 0; j < 2; j++)
            LDSM_X4(bf[j][0], bf[j][1], bf[j][2], bf[j][3], stb + ofsB[j]);
#pragma unroll
        for (int fm = 0; fm < 4; fm++)
#pragma unroll
            for (int fn = 0; fn < 4; fn++)
                mma_f16(acc[fm][fn], af[fm], &bf[fn >> 1][(fn & 1) << 1]);
    }
    CP_WAITALL();

    // -------- epilogue: transpose via smem, bias+relu, coalesced stores --------
    __syncthreads();
    float* Dsh = sh;                                   // [128 n][DST]
    int g = lane >> 2, t = lane & 3;
#pragma unroll
    for (int fm = 0; fm < 4; fm++) {
        int m = (wm << 6) + (fm << 4) + g;
#pragma unroll
        for (int fn = 0; fn < 4; fn++) {
            int n = (wn << 5) + (fn << 3) + (t << 1);
            Dsh[n * DST + m]           = acc[fm][fn][0];
            Dsh[(n + 1) * DST + m]     = acc[fm][fn][1];
            Dsh[n * DST + m + 8]       = acc[fm][fn][2];
            Dsh[(n + 1) * DST + m + 8] = acc[fm][fn][3];
        }
    }
    __syncthreads();
    for (int i = tid; i < 4096; i += 256) {
        int n = i >> 5, cc = (i & 31) << 2;
        int pos = NB + n;
        if (pos < Npos) {
            float4 v = *reinterpret_cast<float4*>(&Dsh[n * DST + cc]);
            v.x = fmaxf(v.x + __ldg(&bias[M0 + cc + 0]), 0.f);
            v.y = fmaxf(v.y + __ldg(&bias[M0 + cc + 1]), 0.f);
            v.z = fmaxf(v.z + __ldg(&bias[M0 + cc + 2]), 0.f);
            v.w = fmaxf(v.w + __ldg(&bias[M0 + cc + 3]), 0.f);
            *reinterpret_cast<float4*>(outp + (bq + pos) * Cout + M0 + cc) = v;
        }
    }
}

// ---------------- pool1: g_c1 (34^3 pos-major) -> d_out l1 (fp32) + g_l1h (fp16) ----------------
__global__ __launch_bounds__(128) void pool1_kernel(float* __restrict__ dout) {
    int pp = blockIdx.x;              // pooled pos in 16^3
    int b = blockIdx.z;
    int P0 = pp >> 8, P1 = (pp >> 4) & 15, P2 = pp & 15;
    int co4 = threadIdx.x << 2;

    float4 m = make_float4(-1e30f, -1e30f, -1e30f, -1e30f);
#pragma unroll
    for (int a = 0; a < 8; a++) {
        int c = (2 * P0 + (a >> 2) + 1) * (SP1 * SP1) + (2 * P1 + ((a >> 1) & 1) + 1) * SP1 + (2 * P2 + (a & 1) + 1);
        float4 v = *reinterpret_cast<const float4*>(&g_c1[((long)b * NPAD1 + c) * C1 + co4]);
        m.x = fmaxf(m.x, v.x); m.y = fmaxf(m.y, v.y); m.z = fmaxf(m.z, v.z); m.w = fmaxf(m.w, v.w);
    }
    int pad2 = (P0 + 1) * (SP2 * SP2) + (P1 + 1) * SP2 + (P2 + 1);
    __half2* lh = reinterpret_cast<__half2*>(&g_l1h[((long)b * NPAD2 + pad2) * C1 + co4]);
    lh[0] = __floats2half2_rn(m.x, m.y);
    lh[1] = __floats2half2_rn(m.z, m.w);

    long ob = ((long)b * 1024 + co4) * 4096 + pp;
    dout[ob] = m.x; dout[ob + 4096] = m.y; dout[ob + 2 * 4096] = m.z; dout[ob + 3 * 4096] = m.w;
}

// ---------------- pool2: g_c2 (18^3 pos-major) -> g_l2 (chan-major 8^3) ----------------
__global__ __launch_bounds__(256) void pool2_kernel() {
    int pp = blockIdx.x;              // pooled pos in 8^3
    int b = blockIdx.z;
    int Q0 = pp >> 6, Q1 = (pp >> 3) & 7, Q2 = pp & 7;
    int co4 = threadIdx.x << 2;

    float4 m = make_float4(-1e30f, -1e30f, -1e30f, -1e30f);
#pragma unroll
    for (int a = 0; a < 8; a++) {
        int c = (2 * Q0 + (a >> 2) + 1) * (SP2 * SP2) + (2 * Q1 + ((a >> 1) & 1) + 1) * SP2 + (2 * Q2 + (a & 1) + 1);
        float4 v = *reinterpret_cast<const float4*>(&g_c2[((long)b * NPAD2 + c) * C2 + co4]);
        m.x = fmaxf(m.x, v.x); m.y = fmaxf(m.y, v.y); m.z = fmaxf(m.z, v.z); m.w = fmaxf(m.w, v.w);
    }
    long ob = ((long)b * 1024 + co4) * 512 + pp;
    g_l2[ob] = m.x; g_l2[ob + 512] = m.y; g_l2[ob + 2 * 512] = m.z; g_l2[ob + 3 * 512] = m.w;
}

// ---------------- convT: 8 parity GEMMs (FFMA) ----------------
__global__ __launch_bounds__(256) void convt_kernel(const float* __restrict__ bt, float* __restrict__ out) {
    __shared__ float w_sh[32 * 128];
    __shared__ float x_sh[32 * 64];
    int posT = blockIdx.x;
    int coT  = blockIdx.y;
    int bp   = blockIdx.z;
    int b = bp >> 3, par = bp & 7;
    int tid = threadIdx.x;
    int col = tid & 31, prow = tid >> 5;

    const float* wbase = g_WtT + (long)par * (1024 * 512);
    const float* xbase = g_l2 + (long)b * (C2 * 512);

    float acc[4][8];
#pragma unroll
    for (int jc = 0; jc < 4; jc++)
#pragma unroll
        for (int jp = 0; jp < 8; jp++) acc[jc][jp] = 0.0f;

    for (int ci0 = 0; ci0 < 1024; ci0 += 32) {
        __syncthreads();
        for (int idx = tid; idx < 32 * 128; idx += 256) {
            int k = idx >> 7, c = idx & 127;
            w_sh[idx] = wbase[(long)(ci0 + k) * 512 + coT * 128 + c];
        }
        for (int idx = tid; idx < 32 * 64; idx += 256) {
            int k = idx >> 6, p = idx & 63;
            x_sh[idx] = xbase[(long)(ci0 + k) * 512 + posT * 64 + p];
        }
        __syncthreads();
#pragma unroll 4
        for (int k = 0; k < 32; k++) {
            float xv[8], wv[4];
#pragma unroll
            for (int jp = 0; jp < 8; jp++) xv[jp] = x_sh[k * 64 + prow + 8 * jp];
#pragma unroll
            for (int jc = 0; jc < 4; jc++) wv[jc] = w_sh[k * 128 + col + 32 * jc];
#pragma unroll
            for (int jc = 0; jc < 4; jc++)
#pragma unroll
                for (int jp = 0; jp < 8; jp++) acc[jc][jp] = fmaf(wv[jc], xv[jp], acc[jc][jp]);
        }
    }

    int az = par >> 2, ay = (par >> 1) & 1, ax = par & 1;
#pragma unroll
    for (int jc = 0; jc < 4; jc++) {
        int co = coT * 128 + col + 32 * jc;
        float bv = __ldg(&bt[co]);
#pragma unroll
        for (int jp = 0; jp < 8; jp++) {
            int pos = posT * 64 + prow + 8 * jp;
            int iz = pos >> 6, iy = (pos >> 3) & 7, ix = pos & 7;
            int s = (2 * iz + az) * 256 + (2 * iy + ay) * 16 + (2 * ix + ax);
            out[((long)b * 1024 + 512 + co) * 4096 + s] = acc[jc][jp] + bv;
        }
    }
}

// ---------------- launcher ----------------
extern "C" void kernel_launch(void* const* d_in, const int* in_sizes, int n_in,
                              void* d_out, int out_size)
{
    const float* pc  = (const float*)d_in[0];
    const float* W1  = (const float*)d_in[1];
    const float* b1  = (const float*)d_in[2];
    const float* W2  = (const float*)d_in[3];
    const float* b2  = (const float*)d_in[4];
    const float* Wc1 = (const float*)d_in[5];
    const float* bc1 = (const float*)d_in[6];
    const float* Wc2 = (const float*)d_in[7];
    const float* bc2 = (const float*)d_in[8];
    const float* Wt  = (const float*)d_in[9];
    const float* bt  = (const float*)d_in[10];
    float* out = (float*)d_out;

    void *p_xpad, *p_xh, *p_wk1, *p_wk2, *p_c1, *p_l1h, *p_c2;
    cudaGetSymbolAddress(&p_xpad, g_xpad);
    cudaGetSymbolAddress(&p_xh, g_xh);
    cudaGetSymbolAddress(&p_wk1, g_wk1);
    cudaGetSymbolAddress(&p_wk2, g_wk2);
    cudaGetSymbolAddress(&p_c1, g_c1);
    cudaGetSymbolAddress(&p_l1h, g_l1h);
    cudaGetSymbolAddress(&p_c2, g_c2);

    const int smem_pf = (128 * 257 + 128 * 65) * 4;           // 164,864 B
    const int smem_gm = 128 * DST * 4;                        // 67,584 B (>= 4*STAGE_B=49,152)
    cudaFuncSetAttribute(point_f_scatter_kernel, cudaFuncAttributeMaxDynamicSharedMemorySize, smem_pf);
    cudaFuncSetAttribute(gemm_conv_h, cudaFuncAttributeMaxDynamicSharedMemorySize, smem_gm);

    // interior-only position ranges (everything pools read)
    const int NBASE1 = SP1 * SP1 + SP1 + 1;                   // 1191
    const int NT1 = (32 * (SP1 * SP1 + SP1 + 1) + 1 - NBASE1 + 127) / 128;  // 289
    const int NBASE2 = SP2 * SP2 + SP2 + 1;                   // 343
    const int NT2 = (16 * (SP2 * SP2 + SP2 + 1) + 1 - NBASE2 + 127) / 128;  // 41

    // 1. zero scatter targets (replay-safe)
    zero_scratch_kernel<<<2048, 256>>>();
    // 2. weight transposes (conv weights -> fp16 [k][co][ci])
    wt_transpose_kernel<<<(8 * 1024 * 512 + 255) / 256, 256>>>(Wt);
    wk_transpose_kernel<<<4096, 256>>>(Wc1, (__half*)p_wk1, C1, C0);
    wk_transpose_kernel<<<8192, 256>>>(Wc2, (__half*)p_wk2, C2, C1);
    // 3. point MLP + scatter (fp32 atomics)
    point_h_kernel<<<TOTPTS / 8, 256>>>(pc, W1, b1);
    point_f_scatter_kernel<<<TOTPTS / 64, 256, smem_pf>>>(W2, b2);
    // 3b. pack fp32 grid -> fp16
    pack_half_kernel<<<2048, 256>>>((const float*)p_xpad, (__half*)p_xh, (long)(BATCH * NPAD1 * C0) / 4);
    // 4. conv1: fp16 mma GEMM over interior positions
    gemm_conv_h<<<dim3(NT1, C1 / 128, BATCH), 256, smem_gm>>>(
        (const __half*)p_wk1, (const __half*)p_xh, bc1, (float*)p_c1, C0, 4, SP1, NPAD1, C1, NBASE1);
    // 5. pool1 -> d_out[:,0:512,:] (fp32) and g_l1h (fp16)
    pool1_kernel<<<dim3(4096, 1, BATCH), 128>>>(out);
    // 6. conv2: fp16 mma GEMM over interior positions
    gemm_conv_h<<<dim3(NT2, C2 / 128, BATCH), 256, smem_gm>>>(
        (const __half*)p_wk2, (const __half*)p_l1h, bc2, (float*)p_c2, C1, 5, SP2, NPAD2, C2, NBASE2);
    // 7. pool2 -> g_l2
    pool2_kernel<<<dim3(512, 1, BATCH), 256>>>();
    // 8. convT -> d_out[:,512:1024,:]
    convt_kernel<<<dim3(8, 4, 16), 256>>>(bt, out);
}